// round 2
// baseline (speedup 1.0000x reference)
#include <cuda_runtime.h>
#include <cstdint>
#include <cstddef>

// Problem shape (fixed by reference)
#define SEQB   4
#define SEQN   2048
#define DMODEL 1024
#define NHEAD  16
#define DHEAD  64
#define MTOT   (SEQB*SEQN)   // 8192

// ---------------- scratch (allocation-free: __device__ globals) ----------------
__device__ float g_Q[MTOT*DMODEL];
__device__ float g_K[MTOT*DMODEL];
__device__ float g_V[MTOT*DMODEL];
__device__ float g_Aout[MTOT*DMODEL];

// ---------------- helpers ----------------
__device__ __forceinline__ unsigned tf32r(float x){
    unsigned u; asm("cvt.rna.tf32.f32 %0, %1;" : "=r"(u) : "f"(x)); return u;
}
__device__ __forceinline__ float tf32f(float x){ return __uint_as_float(tf32r(x)); }

// m16n8k8 tf32 mma, row.col, fp32 accumulate
__device__ __forceinline__ void mma8(float c[4], const unsigned a[4], const unsigned b[2]){
    asm volatile("mma.sync.aligned.m16n8k8.row.col.f32.tf32.tf32.f32 "
        "{%0,%1,%2,%3},{%4,%5,%6,%7},{%8,%9},{%0,%1,%2,%3};\n"
        : "+f"(c[0]), "+f"(c[1]), "+f"(c[2]), "+f"(c[3])
        : "r"(a[0]), "r"(a[1]), "r"(a[2]), "r"(a[3]), "r"(b[0]), "r"(b[1]));
}

// ---------------- TN GEMM: C[M,N] = A[M,K] * W[N,K]^T (all fp32, tf32 mma) ----------------
#define BM 128
#define BN 128
#define BK 32
#define LDAS (BK+4)   // 36 floats: fragment LDS is bank-conflict-free

__global__ void __launch_bounds__(256,1) gemm_tn(const float* __restrict__ A,
        const float* __restrict__ W, float* __restrict__ C, int M, int N, int K)
{
    __shared__ float As[BM*LDAS];
    __shared__ float Bs[BN*LDAS];
    const int tid  = threadIdx.x;
    const int warp = tid >> 5, lane = tid & 31;
    const int wm = warp >> 1, wn = warp & 1;       // 4 x 2 warp grid
    const int group = lane >> 2, tig = lane & 3;
    const int m0 = blockIdx.y * BM, n0 = blockIdx.x * BN;

    float acc[2][8][4];
    #pragma unroll
    for (int i=0;i<2;i++)
        #pragma unroll
        for (int j=0;j<8;j++)
            #pragma unroll
            for (int q=0;q<4;q++) acc[i][j][q]=0.f;

    for (int k0=0; k0<K; k0+=BK){
        // stage A tile (tf32-rounded)
        for (int i=tid; i<BM*BK/4; i+=256){
            int r = i >> 3, c = (i & 7) << 2;
            float4 v = *reinterpret_cast<const float4*>(&A[(size_t)(m0+r)*K + k0 + c]);
            float* d = &As[r*LDAS + c];
            d[0]=tf32f(v.x); d[1]=tf32f(v.y); d[2]=tf32f(v.z); d[3]=tf32f(v.w);
        }
        // stage B tile: Bs[n][k] = W[n0+n][k0+k]
        for (int i=tid; i<BN*BK/4; i+=256){
            int r = i >> 3, c = (i & 7) << 2;
            float4 v = *reinterpret_cast<const float4*>(&W[(size_t)(n0+r)*K + k0 + c]);
            float* d = &Bs[r*LDAS + c];
            d[0]=tf32f(v.x); d[1]=tf32f(v.y); d[2]=tf32f(v.z); d[3]=tf32f(v.w);
        }
        __syncthreads();

        #pragma unroll
        for (int ks=0; ks<BK; ks+=8){
            unsigned af[2][4];
            #pragma unroll
            for (int mf=0; mf<2; mf++){
                int r = wm*32 + mf*16;
                af[mf][0]=__float_as_uint(As[(r+group  )*LDAS + ks+tig  ]);
                af[mf][1]=__float_as_uint(As[(r+group+8)*LDAS + ks+tig  ]);
                af[mf][2]=__float_as_uint(As[(r+group  )*LDAS + ks+tig+4]);
                af[mf][3]=__float_as_uint(As[(r+group+8)*LDAS + ks+tig+4]);
            }
            #pragma unroll
            for (int nf=0; nf<8; nf++){
                int nn = wn*64 + nf*8;
                unsigned bf[2];
                bf[0]=__float_as_uint(Bs[(nn+group)*LDAS + ks+tig  ]);
                bf[1]=__float_as_uint(Bs[(nn+group)*LDAS + ks+tig+4]);
                mma8(acc[0][nf], af[0], bf);
                mma8(acc[1][nf], af[1], bf);
            }
        }
        __syncthreads();
    }

    #pragma unroll
    for (int mf=0; mf<2; mf++){
        #pragma unroll
        for (int nf=0; nf<8; nf++){
            int r  = m0 + wm*32 + mf*16 + group;
            int cc = n0 + wn*64 + nf*8 + 2*tig;
            *reinterpret_cast<float2*>(&C[(size_t)r*N + cc])     = make_float2(acc[mf][nf][0], acc[mf][nf][1]);
            *reinterpret_cast<float2*>(&C[(size_t)(r+8)*N + cc]) = make_float2(acc[mf][nf][2], acc[mf][nf][3]);
        }
    }
}

// ---------------- Flash attention (tf32 mma, online softmax) ----------------
// Per CTA: one (b, h, 64-row q tile). 256 threads = 8 warps in a 4(m) x 2(n) grid.
// Iterate over 64-key tiles: S = Q*K^T -> smem -> softmax update -> P*V accumulate.
#define AQ 64
#define AK 64
#define LDF (DHEAD+4)   // 68 floats padded stride

#define ATTN_SMEM_BYTES ((AQ*LDF + AK*LDF + AK*LDF + AQ*LDF + 2*AQ) * 4)

__global__ void __launch_bounds__(256,2) attn_flash(const float* __restrict__ Q,
        const float* __restrict__ K, const float* __restrict__ V, float* __restrict__ O)
{
    extern __shared__ float sm[];
    float* Qs   = sm;
    float* Ks   = Qs + AQ*LDF;
    float* Vs   = Ks + AK*LDF;
    float* Ss   = Vs + AK*LDF;
    float* alps = Ss + AQ*LDF;   // [AQ] per-row rescale factor
    float* lsum = alps + AQ;     // [AQ] final denominators

    const int b = blockIdx.z, h = blockIdx.y, qt = blockIdx.x;
    const int tid = threadIdx.x, warp = tid >> 5, lane = tid & 31;
    const int wm = warp >> 1, wn = warp & 1;
    const int group = lane >> 2, tig = lane & 3;
    const int qrow0 = b*SEQN + qt*AQ;
    const int hc = h*DHEAD;
    const float scale = 0.125f;  // 1/sqrt(64), folded into Q

    // stage Q (scaled, tf32-rounded); stays resident all iterations
    for (int i=tid; i<AQ*DHEAD/4; i+=256){
        int r = i >> 4, c = (i & 15) << 2;
        float4 v = *reinterpret_cast<const float4*>(&Q[(size_t)(qrow0+r)*DMODEL + hc + c]);
        float* d = &Qs[r*LDF + c];
        d[0]=tf32f(v.x*scale); d[1]=tf32f(v.y*scale);
        d[2]=tf32f(v.z*scale); d[3]=tf32f(v.w*scale);
    }

    // softmax ownership: 4 consecutive lanes per row (shfl-reducible)
    const int srow = tid >> 2, sq = tid & 3;
    float m_r = -1e30f, l_r = 0.f;

    float oacc[4][4];
    #pragma unroll
    for (int i=0;i<4;i++)
        #pragma unroll
        for (int j=0;j<4;j++) oacc[i][j]=0.f;

    for (int kt=0; kt<SEQN/AK; ++kt){
        const int krow0 = b*SEQN + kt*AK;
        for (int i=tid; i<AK*DHEAD/4; i+=256){
            int r = i >> 4, c = (i & 15) << 2;
            float4 kv = *reinterpret_cast<const float4*>(&K[(size_t)(krow0+r)*DMODEL + hc + c]);
            float4 vv = *reinterpret_cast<const float4*>(&V[(size_t)(krow0+r)*DMODEL + hc + c]);
            float* dk = &Ks[r*LDF + c];
            dk[0]=tf32f(kv.x); dk[1]=tf32f(kv.y); dk[2]=tf32f(kv.z); dk[3]=tf32f(kv.w);
            float* dv = &Vs[r*LDF + c];
            dv[0]=tf32f(vv.x); dv[1]=tf32f(vv.y); dv[2]=tf32f(vv.z); dv[3]=tf32f(vv.w);
        }
        __syncthreads();

        // S(16x32 per warp) = Q * K^T
        float sacc[4][4];
        #pragma unroll
        for (int i=0;i<4;i++)
            #pragma unroll
            for (int j=0;j<4;j++) sacc[i][j]=0.f;

        #pragma unroll
        for (int ks=0; ks<DHEAD; ks+=8){
            unsigned af[4];
            const int r = wm*16;
            af[0]=__float_as_uint(Qs[(r+group  )*LDF + ks+tig  ]);
            af[1]=__float_as_uint(Qs[(r+group+8)*LDF + ks+tig  ]);
            af[2]=__float_as_uint(Qs[(r+group  )*LDF + ks+tig+4]);
            af[3]=__float_as_uint(Qs[(r+group+8)*LDF + ks+tig+4]);
            #pragma unroll
            for (int nf=0; nf<4; nf++){
                int nn = wn*32 + nf*8;
                unsigned bf[2];
                bf[0]=__float_as_uint(Ks[(nn+group)*LDF + ks+tig  ]);
                bf[1]=__float_as_uint(Ks[(nn+group)*LDF + ks+tig+4]);
                mma8(sacc[nf], af, bf);
            }
        }
        #pragma unroll
        for (int nf=0; nf<4; nf++){
            int r  = wm*16 + group;
            int cc = wn*32 + nf*8 + 2*tig;
            Ss[r*LDF + cc]       = sacc[nf][0];
            Ss[r*LDF + cc+1]     = sacc[nf][1];
            Ss[(r+8)*LDF + cc]   = sacc[nf][2];
            Ss[(r+8)*LDF + cc+1] = sacc[nf][3];
        }
        __syncthreads();

        // online softmax: 4 lanes per row, 16 cols each
        {
            float sv[16];
            float pmax = -1e30f;
            const int c0 = sq*16;
            #pragma unroll
            for (int j=0;j<16;j++){ sv[j]=Ss[srow*LDF + c0 + j]; pmax=fmaxf(pmax, sv[j]); }
            pmax = fmaxf(pmax, __shfl_xor_sync(0xffffffffu, pmax, 1));
            pmax = fmaxf(pmax, __shfl_xor_sync(0xffffffffu, pmax, 2));
            const float m_new = fmaxf(m_r, pmax);
            const float a = __expf(m_r - m_new);
            float psum = 0.f;
            #pragma unroll
            for (int j=0;j<16;j++){
                float p = __expf(sv[j] - m_new);
                psum += p;
                Ss[srow*LDF + c0 + j] = tf32f(p);
            }
            psum += __shfl_xor_sync(0xffffffffu, psum, 1);
            psum += __shfl_xor_sync(0xffffffffu, psum, 2);
            l_r = l_r*a + psum;
            m_r = m_new;
            if (sq == 0) alps[srow] = a;
        }
        __syncthreads();

        // O = O*alpha + P*V
        const float a_lo = alps[wm*16 + group];
        const float a_hi = alps[wm*16 + group + 8];
        #pragma unroll
        for (int nf=0; nf<4; nf++){
            oacc[nf][0]*=a_lo; oacc[nf][1]*=a_lo;
            oacc[nf][2]*=a_hi; oacc[nf][3]*=a_hi;
        }
        #pragma unroll
        for (int ks=0; ks<AK; ks+=8){
            unsigned af[4];
            const int r = wm*16;
            af[0]=__float_as_uint(Ss[(r+group  )*LDF + ks+tig  ]);
            af[1]=__float_as_uint(Ss[(r+group+8)*LDF + ks+tig  ]);
            af[2]=__float_as_uint(Ss[(r+group  )*LDF + ks+tig+4]);
            af[3]=__float_as_uint(Ss[(r+group+8)*LDF + ks+tig+4]);
            #pragma unroll
            for (int nf=0; nf<4; nf++){
                int nn = wn*32 + nf*8;
                unsigned bf[2];
                bf[0]=__float_as_uint(Vs[(ks+tig  )*LDF + nn+group]);
                bf[1]=__float_as_uint(Vs[(ks+tig+4)*LDF + nn+group]);
                mma8(oacc[nf], af, bf);
            }
        }
        __syncthreads();
    }

    if (sq == 0) lsum[srow] = l_r;
    __syncthreads();
    const float inv_lo = 1.f / lsum[wm*16 + group];
    const float inv_hi = 1.f / lsum[wm*16 + group + 8];
    #pragma unroll
    for (int nf=0; nf<4; nf++){
        int r  = qrow0 + wm*16 + group;
        int cc = hc + wn*32 + nf*8 + 2*tig;
        *reinterpret_cast<float2*>(&O[(size_t)r*DMODEL + cc]) =
            make_float2(oacc[nf][0]*inv_lo, oacc[nf][1]*inv_lo);
        *reinterpret_cast<float2*>(&O[(size_t)(r+8)*DMODEL + cc]) =
            make_float2(oacc[nf][2]*inv_hi, oacc[nf][3]*inv_hi);
    }
}

// ---------------- launch ----------------
extern "C" void kernel_launch(void* const* d_in, const int* in_sizes, int n_in,
                              void* d_out, int out_size)
{
    (void)in_sizes; (void)n_in; (void)out_size;
    const float* x  = (const float*)d_in[0];
    const float* Wq = (const float*)d_in[1];
    const float* Wk = (const float*)d_in[2];
    const float* Wv = (const float*)d_in[3];
    const float* Wo = (const float*)d_in[4];
    float* out = (float*)d_out;

    float *q, *k, *v, *aout;
    cudaGetSymbolAddress((void**)&q,    g_Q);
    cudaGetSymbolAddress((void**)&k,    g_K);
    cudaGetSymbolAddress((void**)&v,    g_V);
    cudaGetSymbolAddress((void**)&aout, g_Aout);

    cudaFuncSetAttribute(attn_flash, cudaFuncAttributeMaxDynamicSharedMemorySize,
                         ATTN_SMEM_BYTES);

    dim3 g1(DMODEL/BN, MTOT/BM);   // (8, 64)
    gemm_tn<<<g1, 256>>>(x, Wq, q, MTOT, DMODEL, DMODEL);
    gemm_tn<<<g1, 256>>>(x, Wk, k, MTOT, DMODEL, DMODEL);
    gemm_tn<<<g1, 256>>>(x, Wv, v, MTOT, DMODEL, DMODEL);

    dim3 g2(SEQN/AQ, NHEAD, SEQB); // (32, 16, 4)
    attn_flash<<<g2, 256, ATTN_SMEM_BYTES>>>(q, k, v, aout);

    gemm_tn<<<g1, 256>>>(aout, Wo, out, MTOT, DMODEL, DMODEL);
}

// round 5
// speedup vs baseline: 1.7882x; 1.7882x over previous
#include <cuda_runtime.h>
#include <cstdint>
#include <cstddef>

// Problem shape (fixed by reference)
#define SEQB   4
#define SEQN   2048
#define DMODEL 1024
#define NHEAD  16
#define DHEAD  64
#define MTOT   (SEQB*SEQN)   // 8192

// ---------------- scratch (allocation-free: __device__ globals) ----------------
__device__ float g_Q[MTOT*DMODEL];
__device__ float g_K[MTOT*DMODEL];
__device__ float g_V[MTOT*DMODEL];
__device__ float g_Aout[MTOT*DMODEL];   // attention output, pre-rounded+permuted
__device__ float g_Xr[MTOT*DMODEL];     // x, tf32-rounded + k-interleaved
__device__ float g_Wqr[DMODEL*DMODEL];
__device__ float g_Wkr[DMODEL*DMODEL];
__device__ float g_Wvr[DMODEL*DMODEL];
__device__ float g_Wor[DMODEL*DMODEL];

// ---------------- helpers ----------------
__device__ __forceinline__ unsigned tf32r(float x){
    unsigned u; asm("cvt.rna.tf32.f32 %0, %1;" : "=r"(u) : "f"(x)); return u;
}
__device__ __forceinline__ float tf32f(float x){ return __uint_as_float(tf32r(x)); }
__device__ __forceinline__ float ex2f(float x){
    float r; asm("ex2.approx.f32 %0, %1;" : "=f"(r) : "f"(x)); return r;
}
__device__ __forceinline__ uint32_t smem_u32(const void* p){
    uint32_t a; asm("{ .reg .u64 t; cvta.to.shared.u64 t, %1; cvt.u32.u64 %0, t; }" : "=r"(a) : "l"(p));
    return a;
}
__device__ __forceinline__ void cp16(uint32_t sdst, const void* gsrc){
    asm volatile("cp.async.cg.shared.global [%0], [%1], 16;" :: "r"(sdst), "l"(gsrc) : "memory");
}
#define CP_COMMIT()  asm volatile("cp.async.commit_group;" ::: "memory")
#define CP_WAIT(N)   asm volatile("cp.async.wait_group %0;" :: "n"(N) : "memory")

// m16n8k8 tf32 mma, row.col, fp32 accumulate
__device__ __forceinline__ void mma8(float c[4], const unsigned a[4], const unsigned b[2]){
    asm volatile("mma.sync.aligned.m16n8k8.row.col.f32.tf32.tf32.f32 "
        "{%0,%1,%2,%3},{%4,%5,%6,%7},{%8,%9},{%0,%1,%2,%3};\n"
        : "+f"(c[0]), "+f"(c[1]), "+f"(c[2]), "+f"(c[3])
        : "r"(a[0]), "r"(a[1]), "r"(a[2]), "r"(a[3]), "r"(b[0]), "r"(b[1]));
}

// ---------------- prep: tf32-round + k-pair interleave ----------------
// Permuted layout P: within each 8-col block, P[s] = tf32(R[(s>>1) + (s&1)*4]).
// Then fragment pairs (k, k+4) sit at adjacent floats (s=2t, 2t+1) -> LDS.64.
__global__ void __launch_bounds__(256) prep(const float* __restrict__ in,
                                            float* __restrict__ out, int n)
{
    int i = blockIdx.x*256 + threadIdx.x;
    if (i < n){
        int s = i & 7, base = i & ~7;
        int k = (s >> 1) + ((s & 1) << 2);
        out[i] = tf32f(in[base + k]);
    }
}

// ================= GEMM: C[M,N] = A[M,K] * W[N,K]^T =================
// A, W pre-rounded + k-interleaved. CTA 256x128, 8 warps (4m x 2n) of 64x64.
// cp.async 3-stage pipeline, BK=32, LDS.64 conflict-free fragment loads.
#define GBM 256
#define GBN 128
#define GBK 32
#define LDR 40                       // floats per smem row (bank-conflict-free)
#define STG_A  (GBM*LDR)             // 10240 floats
#define STG_B  (GBN*LDR)             // 5120 floats
#define STG_F  (STG_A + STG_B)       // 15360 floats per stage
#define GEMM_SMEM (3*STG_F*4)        // 184320 bytes

__global__ void __launch_bounds__(256,1) gemm_tc2(const float* __restrict__ A,
        const float* __restrict__ W, float* __restrict__ C, int M, int N, int K)
{
    extern __shared__ float sf[];
    const uint32_t sb = smem_u32(sf);
    const int tid = threadIdx.x, wid = tid >> 5, lane = tid & 31;
    const int wm = wid >> 1, wn = wid & 1;
    const int group = lane >> 2, tig = lane & 3;
    const int m0 = blockIdx.y * GBM, n0 = blockIdx.x * GBN;
    const int rA = wm*64, cB = wn*64;

    float acc[4][8][4];
    #pragma unroll
    for (int i=0;i<4;i++)
        #pragma unroll
        for (int j=0;j<8;j++)
            #pragma unroll
            for (int q=0;q<4;q++) acc[i][j][q]=0.f;

    const int ntiles = K >> 5;   // 32

    // ---- stage issuer ----
    auto issue = [&](int st, int kt){
        const uint32_t sA = sb + (uint32_t)(st*STG_F)*4u;
        const uint32_t sB = sA + STG_A*4u;
        #pragma unroll
        for (int i=0;i<8;i++){
            int j = tid + 256*i, r = j>>3, c4 = j&7;
            cp16(sA + (uint32_t)(r*LDR + c4*4)*4u,
                 &A[(size_t)(m0+r)*K + kt*GBK + c4*4]);
        }
        #pragma unroll
        for (int i=0;i<4;i++){
            int j = tid + 256*i, r = j>>3, c4 = j&7;
            cp16(sB + (uint32_t)(r*LDR + c4*4)*4u,
                 &W[(size_t)(n0+r)*K + kt*GBK + c4*4]);
        }
        CP_COMMIT();
    };

    issue(0, 0);
    issue(1, 1);

    for (int t = 0; t < ntiles; ++t){
        const int st = t % 3;
        CP_WAIT(1);
        __syncthreads();
        if (t + 2 < ntiles) issue((t+2)%3, t+2);
        else CP_COMMIT();   // keep group count aligned

        const float* sA = sf + st*STG_F;
        const float* sB = sA + STG_A;

        #pragma unroll
        for (int ks=0; ks<GBK; ks+=8){
            float2 alo[4], ahi[4];
            #pragma unroll
            for (int mf=0; mf<4; mf++){
                int r = rA + mf*16 + group;
                alo[mf] = *reinterpret_cast<const float2*>(&sA[r*LDR + ks + 2*tig]);
                ahi[mf] = *reinterpret_cast<const float2*>(&sA[(r+8)*LDR + ks + 2*tig]);
            }
            #pragma unroll
            for (int nf=0; nf<8; nf++){
                int c = cB + nf*8 + group;
                float2 b = *reinterpret_cast<const float2*>(&sB[c*LDR + ks + 2*tig]);
                unsigned bf[2] = { __float_as_uint(b.x), __float_as_uint(b.y) };
                #pragma unroll
                for (int mf=0; mf<4; mf++){
                    unsigned af[4] = { __float_as_uint(alo[mf].x), __float_as_uint(ahi[mf].x),
                                       __float_as_uint(alo[mf].y), __float_as_uint(ahi[mf].y) };
                    mma8(acc[mf][nf], af, bf);
                }
            }
        }
        __syncthreads();
    }

    // epilogue: fp32 stores
    #pragma unroll
    for (int mf=0; mf<4; mf++){
        const size_t r0 = (size_t)(m0 + rA + mf*16 + group);
        #pragma unroll
        for (int nf=0; nf<8; nf++){
            const int cc = n0 + cB + nf*8 + 2*tig;
            *reinterpret_cast<float2*>(&C[r0*N + cc]) =
                make_float2(acc[mf][nf][0], acc[mf][nf][1]);
            *reinterpret_cast<float2*>(&C[(r0+8)*N + cc]) =
                make_float2(acc[mf][nf][2], acc[mf][nf][3]);
        }
    }
}

// ---------------- Flash attention (legacy tf32 mma, online softmax) ----------------
#define AQ 64
#define AK 64
#define LDF (DHEAD+4)
#define ATTN_SMEM_BYTES ((AQ*LDF + AK*LDF + AK*LDF + AQ*LDF + 2*AQ) * 4)

// permuted column position within 8-block (for g_Aout, O-proj GEMM input)
__device__ __forceinline__ int kperm(int c){
    return (c & ~7) | ((c & 3) << 1) | ((c >> 2) & 1);
}

__global__ void __launch_bounds__(256,2) attn_flash(const float* __restrict__ Q,
        const float* __restrict__ K, const float* __restrict__ V, float* __restrict__ O)
{
    extern __shared__ float sm[];
    float* Qs   = sm;
    float* Ks   = Qs + AQ*LDF;
    float* Vs   = Ks + AK*LDF;
    float* Ss   = Vs + AK*LDF;
    float* alps = Ss + AQ*LDF;
    float* lsum = alps + AQ;

    const int b = blockIdx.z, h = blockIdx.y, qt = blockIdx.x;
    const int tid = threadIdx.x, warp = tid >> 5, lane = tid & 31;
    const int wm = warp >> 1, wn = warp & 1;
    const int group = lane >> 2, tig = lane & 3;
    const int qrow0 = b*SEQN + qt*AQ;
    const int hc = h*DHEAD;
    // 1/sqrt(64) * log2(e): softmax in base 2
    const float scale = 0.125f * 1.4426950408889634f;

    for (int i=tid; i<AQ*DHEAD/4; i+=256){
        int r = i >> 4, c = (i & 15) << 2;
        float4 v = *reinterpret_cast<const float4*>(&Q[(size_t)(qrow0+r)*DMODEL + hc + c]);
        float* d = &Qs[r*LDF + c];
        d[0]=tf32f(v.x*scale); d[1]=tf32f(v.y*scale);
        d[2]=tf32f(v.z*scale); d[3]=tf32f(v.w*scale);
    }

    const int srow = tid >> 2, sq = tid & 3;
    float m_r = -1e30f, l_r = 0.f;

    float oacc[4][4];
    #pragma unroll
    for (int i=0;i<4;i++)
        #pragma unroll
        for (int j=0;j<4;j++) oacc[i][j]=0.f;

    for (int kt=0; kt<SEQN/AK; ++kt){
        const int krow0 = b*SEQN + kt*AK;
        for (int i=tid; i<AK*DHEAD/4; i+=256){
            int r = i >> 4, c = (i & 15) << 2;
            float4 kv = *reinterpret_cast<const float4*>(&K[(size_t)(krow0+r)*DMODEL + hc + c]);
            float4 vv = *reinterpret_cast<const float4*>(&V[(size_t)(krow0+r)*DMODEL + hc + c]);
            float* dk = &Ks[r*LDF + c];
            dk[0]=tf32f(kv.x); dk[1]=tf32f(kv.y); dk[2]=tf32f(kv.z); dk[3]=tf32f(kv.w);
            float* dv = &Vs[r*LDF + c];
            dv[0]=tf32f(vv.x); dv[1]=tf32f(vv.y); dv[2]=tf32f(vv.z); dv[3]=tf32f(vv.w);
        }
        __syncthreads();

        float sacc[4][4];
        #pragma unroll
        for (int i=0;i<4;i++)
            #pragma unroll
            for (int j=0;j<4;j++) sacc[i][j]=0.f;

        #pragma unroll
        for (int ks=0; ks<DHEAD; ks+=8){
            unsigned af[4];
            const int r = wm*16;
            af[0]=__float_as_uint(Qs[(r+group  )*LDF + ks+tig  ]);
            af[1]=__float_as_uint(Qs[(r+group+8)*LDF + ks+tig  ]);
            af[2]=__float_as_uint(Qs[(r+group  )*LDF + ks+tig+4]);
            af[3]=__float_as_uint(Qs[(r+group+8)*LDF + ks+tig+4]);
            #pragma unroll
            for (int nf=0; nf<4; nf++){
                int nn = wn*32 + nf*8;
                unsigned bf[2];
                bf[0]=__float_as_uint(Ks[(nn+group)*LDF + ks+tig  ]);
                bf[1]=__float_as_uint(Ks[(nn+group)*LDF + ks+tig+4]);
                mma8(sacc[nf], af, bf);
            }
        }
        #pragma unroll
        for (int nf=0; nf<4; nf++){
            int r  = wm*16 + group;
            int cc = wn*32 + nf*8 + 2*tig;
            Ss[r*LDF + cc]       = sacc[nf][0];
            Ss[r*LDF + cc+1]     = sacc[nf][1];
            Ss[(r+8)*LDF + cc]   = sacc[nf][2];
            Ss[(r+8)*LDF + cc+1] = sacc[nf][3];
        }
        __syncthreads();

        {
            float sv[16];
            float pmax = -1e30f;
            const int c0 = sq*16;
            #pragma unroll
            for (int j=0;j<16;j++){ sv[j]=Ss[srow*LDF + c0 + j]; pmax=fmaxf(pmax, sv[j]); }
            pmax = fmaxf(pmax, __shfl_xor_sync(0xffffffffu, pmax, 1));
            pmax = fmaxf(pmax, __shfl_xor_sync(0xffffffffu, pmax, 2));
            const float m_new = fmaxf(m_r, pmax);
            const float a = ex2f(m_r - m_new);
            float psum = 0.f;
            #pragma unroll
            for (int j=0;j<16;j++){
                float p = ex2f(sv[j] - m_new);
                psum += p;
                Ss[srow*LDF + c0 + j] = tf32f(p);
            }
            psum += __shfl_xor_sync(0xffffffffu, psum, 1);
            psum += __shfl_xor_sync(0xffffffffu, psum, 2);
            l_r = l_r*a + psum;
            m_r = m_new;
            if (sq == 0) alps[srow] = a;
        }
        __syncthreads();

        const float a_lo = alps[wm*16 + group];
        const float a_hi = alps[wm*16 + group + 8];
        #pragma unroll
        for (int nf=0; nf<4; nf++){
            oacc[nf][0]*=a_lo; oacc[nf][1]*=a_lo;
            oacc[nf][2]*=a_hi; oacc[nf][3]*=a_hi;
        }
        #pragma unroll
        for (int ks=0; ks<AK; ks+=8){
            unsigned af[4];
            const int r = wm*16;
            af[0]=__float_as_uint(Ss[(r+group  )*LDF + ks+tig  ]);
            af[1]=__float_as_uint(Ss[(r+group+8)*LDF + ks+tig  ]);
            af[2]=__float_as_uint(Ss[(r+group  )*LDF + ks+tig+4]);
            af[3]=__float_as_uint(Ss[(r+group+8)*LDF + ks+tig+4]);
            #pragma unroll
            for (int nf=0; nf<4; nf++){
                int nn = wn*32 + nf*8;
                unsigned bf[2];
                bf[0]=__float_as_uint(Vs[(ks+tig  )*LDF + nn+group]);
                bf[1]=__float_as_uint(Vs[(ks+tig+4)*LDF + nn+group]);
                mma8(oacc[nf], af, bf);
            }
        }
        __syncthreads();
    }

    if (sq == 0) lsum[srow] = l_r;
    __syncthreads();
    const float inv_lo = 1.f / lsum[wm*16 + group];
    const float inv_hi = 1.f / lsum[wm*16 + group + 8];
    // write O pre-rounded + k-interleaved (it is the A operand of the O-proj GEMM)
    #pragma unroll
    for (int nf=0; nf<4; nf++){
        const size_t r  = (size_t)(qrow0 + wm*16 + group);
        const int cc = hc + wn*32 + nf*8 + 2*tig;
        O[r*DMODEL     + kperm(cc)]   = tf32f(oacc[nf][0]*inv_lo);
        O[r*DMODEL     + kperm(cc+1)] = tf32f(oacc[nf][1]*inv_lo);
        O[(r+8)*DMODEL + kperm(cc)]   = tf32f(oacc[nf][2]*inv_hi);
        O[(r+8)*DMODEL + kperm(cc+1)] = tf32f(oacc[nf][3]*inv_hi);
    }
}

// ---------------- launch ----------------
extern "C" void kernel_launch(void* const* d_in, const int* in_sizes, int n_in,
                              void* d_out, int out_size)
{
    (void)in_sizes; (void)n_in; (void)out_size;
    const float* x  = (const float*)d_in[0];
    const float* Wq = (const float*)d_in[1];
    const float* Wk = (const float*)d_in[2];
    const float* Wv = (const float*)d_in[3];
    const float* Wo = (const float*)d_in[4];
    float* out = (float*)d_out;

    float *q, *k, *v, *aout, *xr, *wqr, *wkr, *wvr, *wor;
    cudaGetSymbolAddress((void**)&q,    g_Q);
    cudaGetSymbolAddress((void**)&k,    g_K);
    cudaGetSymbolAddress((void**)&v,    g_V);
    cudaGetSymbolAddress((void**)&aout, g_Aout);
    cudaGetSymbolAddress((void**)&xr,   g_Xr);
    cudaGetSymbolAddress((void**)&wqr,  g_Wqr);
    cudaGetSymbolAddress((void**)&wkr,  g_Wkr);
    cudaGetSymbolAddress((void**)&wvr,  g_Wvr);
    cudaGetSymbolAddress((void**)&wor,  g_Wor);

    cudaFuncSetAttribute(gemm_tc2, cudaFuncAttributeMaxDynamicSharedMemorySize, GEMM_SMEM);
    cudaFuncSetAttribute(attn_flash, cudaFuncAttributeMaxDynamicSharedMemorySize,
                         ATTN_SMEM_BYTES);

    const int NX = MTOT*DMODEL, NW = DMODEL*DMODEL;
    prep<<<NX/256, 256>>>(x,  xr,  NX);
    prep<<<NW/256, 256>>>(Wq, wqr, NW);
    prep<<<NW/256, 256>>>(Wk, wkr, NW);
    prep<<<NW/256, 256>>>(Wv, wvr, NW);
    prep<<<NW/256, 256>>>(Wo, wor, NW);

    dim3 g1(DMODEL/GBN, MTOT/GBM);   // (8, 32)
    gemm_tc2<<<g1, 256, GEMM_SMEM>>>(xr, wqr, q, MTOT, DMODEL, DMODEL);
    gemm_tc2<<<g1, 256, GEMM_SMEM>>>(xr, wkr, k, MTOT, DMODEL, DMODEL);
    gemm_tc2<<<g1, 256, GEMM_SMEM>>>(xr, wvr, v, MTOT, DMODEL, DMODEL);

    dim3 g2(SEQN/AQ, NHEAD, SEQB);   // (32, 16, 4)
    attn_flash<<<g2, 256, ATTN_SMEM_BYTES>>>(q, k, v, aout);

    gemm_tc2<<<g1, 256, GEMM_SMEM>>>(aout, wor, out, MTOT, DMODEL, DMODEL);
}

// round 6
// speedup vs baseline: 2.8407x; 1.5886x over previous
#include <cuda_runtime.h>
#include <cstdint>
#include <cstddef>

// Problem shape (fixed by reference)
#define SEQB   4
#define SEQN   2048
#define DMODEL 1024
#define NHEAD  16
#define DHEAD  64
#define MTOT   (SEQB*SEQN)   // 8192

// ---------------- scratch (allocation-free: __device__ globals) ----------------
__device__ float g_Q[MTOT*DMODEL];      // tf32-rounded, d-interleaved, scaled
__device__ float g_K[MTOT*DMODEL];      // tf32-rounded, d-interleaved
__device__ float g_V[MTOT*DMODEL];      // tf32-rounded, natural
__device__ float g_Aout[MTOT*DMODEL];   // attention output, rounded + interleaved
__device__ float g_Xr[MTOT*DMODEL];     // x, tf32-rounded + k-interleaved
__device__ float g_Wqr[DMODEL*DMODEL];
__device__ float g_Wkr[DMODEL*DMODEL];
__device__ float g_Wvr[DMODEL*DMODEL];
__device__ float g_Wor[DMODEL*DMODEL];

// ---------------- helpers ----------------
__device__ __forceinline__ unsigned tf32r(float x){
    unsigned u; asm("cvt.rna.tf32.f32 %0, %1;" : "=r"(u) : "f"(x)); return u;
}
__device__ __forceinline__ float tf32f(float x){ return __uint_as_float(tf32r(x)); }
__device__ __forceinline__ float ex2f(float x){
    float r; asm("ex2.approx.f32 %0, %1;" : "=f"(r) : "f"(x)); return r;
}
__device__ __forceinline__ uint32_t smem_u32(const void* p){
    uint32_t a; asm("{ .reg .u64 t; cvta.to.shared.u64 t, %1; cvt.u32.u64 %0, t; }" : "=r"(a) : "l"(p));
    return a;
}
__device__ __forceinline__ void cp16(uint32_t sdst, const void* gsrc){
    asm volatile("cp.async.cg.shared.global [%0], [%1], 16;" :: "r"(sdst), "l"(gsrc) : "memory");
}
#define CP_COMMIT()  asm volatile("cp.async.commit_group;" ::: "memory")
#define CP_WAIT(N)   asm volatile("cp.async.wait_group %0;" :: "n"(N) : "memory")

// m16n8k8 tf32 mma, row.col, fp32 accumulate
__device__ __forceinline__ void mma8(float c[4], const unsigned a[4], const unsigned b[2]){
    asm volatile("mma.sync.aligned.m16n8k8.row.col.f32.tf32.tf32.f32 "
        "{%0,%1,%2,%3},{%4,%5,%6,%7},{%8,%9},{%0,%1,%2,%3};\n"
        : "+f"(c[0]), "+f"(c[1]), "+f"(c[2]), "+f"(c[3])
        : "r"(a[0]), "r"(a[1]), "r"(a[2]), "r"(a[3]), "r"(b[0]), "r"(b[1]));
}

// position of original col c within its interleaved 8-block
__device__ __forceinline__ int kp8(int c){
    return ((c & 3) << 1) | ((c >> 2) & 1);
}

// ---------------- prep: tf32-round + k-pair interleave ----------------
__global__ void __launch_bounds__(256) prep(const float* __restrict__ in,
                                            float* __restrict__ out, int n)
{
    int i = blockIdx.x*256 + threadIdx.x;
    if (i < n){
        int s = i & 7, base = i & ~7;
        int k = (s >> 1) + ((s & 1) << 2);
        out[i] = tf32f(in[base + k]);
    }
}

// ================= GEMM: C[M,N] = A[M,K] * W[N,K]^T =================
// A, W pre-rounded + k-interleaved. CTA 256x128, 8 warps (4m x 2n) of 64x64.
// cp.async 3-stage pipeline, BK=32, LDS.64 conflict-free fragment loads.
// Epilogue modes: 0 = plain fp32; 1 = tf32f(acc*scl), column-interleaved; 2 = tf32f(acc), natural.
#define GBM 256
#define GBN 128
#define GBK 32
#define LDR 40
#define STG_A  (GBM*LDR)
#define STG_B  (GBN*LDR)
#define STG_F  (STG_A + STG_B)
#define GEMM_SMEM (3*STG_F*4)

__global__ void __launch_bounds__(256,1) gemm_tc2(const float* __restrict__ A,
        const float* __restrict__ W, float* __restrict__ C, int M, int N, int K,
        int mode, float scl)
{
    extern __shared__ float sf[];
    const uint32_t sb = smem_u32(sf);
    const int tid = threadIdx.x, wid = tid >> 5, lane = tid & 31;
    const int wm = wid >> 1, wn = wid & 1;
    const int group = lane >> 2, tig = lane & 3;
    const int m0 = blockIdx.y * GBM, n0 = blockIdx.x * GBN;
    const int rA = wm*64, cB = wn*64;

    float acc[4][8][4];
    #pragma unroll
    for (int i=0;i<4;i++)
        #pragma unroll
        for (int j=0;j<8;j++)
            #pragma unroll
            for (int q=0;q<4;q++) acc[i][j][q]=0.f;

    const int ntiles = K >> 5;

    auto issue = [&](int st, int kt){
        const uint32_t sA = sb + (uint32_t)(st*STG_F)*4u;
        const uint32_t sB = sA + STG_A*4u;
        #pragma unroll
        for (int i=0;i<8;i++){
            int j = tid + 256*i, r = j>>3, c4 = j&7;
            cp16(sA + (uint32_t)(r*LDR + c4*4)*4u,
                 &A[(size_t)(m0+r)*K + kt*GBK + c4*4]);
        }
        #pragma unroll
        for (int i=0;i<4;i++){
            int j = tid + 256*i, r = j>>3, c4 = j&7;
            cp16(sB + (uint32_t)(r*LDR + c4*4)*4u,
                 &W[(size_t)(n0+r)*K + kt*GBK + c4*4]);
        }
        CP_COMMIT();
    };

    issue(0, 0);
    issue(1, 1);

    for (int t = 0; t < ntiles; ++t){
        const int st = t % 3;
        CP_WAIT(1);
        __syncthreads();
        if (t + 2 < ntiles) issue((t+2)%3, t+2);
        else CP_COMMIT();

        const float* sA = sf + st*STG_F;
        const float* sB = sA + STG_A;

        #pragma unroll
        for (int ks=0; ks<GBK; ks+=8){
            float2 alo[4], ahi[4];
            #pragma unroll
            for (int mf=0; mf<4; mf++){
                int r = rA + mf*16 + group;
                alo[mf] = *reinterpret_cast<const float2*>(&sA[r*LDR + ks + 2*tig]);
                ahi[mf] = *reinterpret_cast<const float2*>(&sA[(r+8)*LDR + ks + 2*tig]);
            }
            #pragma unroll
            for (int nf=0; nf<8; nf++){
                int c = cB + nf*8 + group;
                float2 b = *reinterpret_cast<const float2*>(&sB[c*LDR + ks + 2*tig]);
                unsigned bf[2] = { __float_as_uint(b.x), __float_as_uint(b.y) };
                #pragma unroll
                for (int mf=0; mf<4; mf++){
                    unsigned af[4] = { __float_as_uint(alo[mf].x), __float_as_uint(ahi[mf].x),
                                       __float_as_uint(alo[mf].y), __float_as_uint(ahi[mf].y) };
                    mma8(acc[mf][nf], af, bf);
                }
            }
        }
        __syncthreads();
    }

    // epilogue
    const int p0 = kp8(2*tig), p1 = kp8(2*tig+1);
    #pragma unroll
    for (int mf=0; mf<4; mf++){
        const size_t r0 = (size_t)(m0 + rA + mf*16 + group);
        #pragma unroll
        for (int nf=0; nf<8; nf++){
            const int base = n0 + cB + nf*8;
            if (mode == 0){
                *reinterpret_cast<float2*>(&C[r0*N + base + 2*tig]) =
                    make_float2(acc[mf][nf][0], acc[mf][nf][1]);
                *reinterpret_cast<float2*>(&C[(r0+8)*N + base + 2*tig]) =
                    make_float2(acc[mf][nf][2], acc[mf][nf][3]);
            } else if (mode == 1){
                C[r0*N     + base + p0] = tf32f(acc[mf][nf][0]*scl);
                C[r0*N     + base + p1] = tf32f(acc[mf][nf][1]*scl);
                C[(r0+8)*N + base + p0] = tf32f(acc[mf][nf][2]*scl);
                C[(r0+8)*N + base + p1] = tf32f(acc[mf][nf][3]*scl);
            } else {
                *reinterpret_cast<float2*>(&C[r0*N + base + 2*tig]) =
                    make_float2(tf32f(acc[mf][nf][0]), tf32f(acc[mf][nf][1]));
                *reinterpret_cast<float2*>(&C[(r0+8)*N + base + 2*tig]) =
                    make_float2(tf32f(acc[mf][nf][2]), tf32f(acc[mf][nf][3]));
            }
        }
    }
}

// ================= Flash attention v2: register-resident S/P =================
// CTA = 128 q rows (8 warps x 16 rows), key tile 64, DHEAD=64.
// Q in registers (permuted+scaled+rounded). K (permuted) / V (natural) staged
// via cp.async double buffer. S and P never touch smem; softmax via shfl.
// PV reuses P accumulator fragments directly with key relabel [2t, 2t+1].
#define QTB 128
#define KTB 64
#define LDK 72
#define LDV 68
#define K_F (KTB*LDK)                 // 4608 floats
#define V_F (KTB*LDV)                 // 4352 floats
#define STAGE_F (K_F + V_F)           // 8960 floats
#define ATTN_SMEM (2*STAGE_F*4)       // 71680 bytes

__global__ void __launch_bounds__(256,1) attn_flash2(const float* __restrict__ Q,
        const float* __restrict__ K, const float* __restrict__ V, float* __restrict__ O)
{
    extern __shared__ float sf[];
    const uint32_t sb = smem_u32(sf);
    const int b = blockIdx.z, h = blockIdx.y, qt = blockIdx.x;
    const int tid = threadIdx.x, warp = tid >> 5, lane = tid & 31;
    const int group = lane >> 2, tig = lane & 3;
    const int qrow0 = b*SEQN + qt*QTB;
    const int hc = h*DHEAD;

    // Q fragments: rows (warp*16+group, +8), 8 chunks of interleaved pairs
    float2 qlo[8], qhi[8];
    {
        const float* qr = &Q[(size_t)(qrow0 + warp*16 + group)*DMODEL + hc];
        #pragma unroll
        for (int c = 0; c < 8; ++c){
            qlo[c] = *reinterpret_cast<const float2*>(&qr[8*c + 2*tig]);
            qhi[c] = *reinterpret_cast<const float2*>(&qr[8*DMODEL + 8*c + 2*tig]);
        }
    }

    float oacc[8][4];
    #pragma unroll
    for (int i=0;i<8;i++)
        #pragma unroll
        for (int j=0;j<4;j++) oacc[i][j]=0.f;
    float m_lo = -1e30f, m_hi = -1e30f, l_lo = 0.f, l_hi = 0.f;

    auto issue = [&](int st, int kt){
        const uint32_t kb = sb + (uint32_t)(st*STAGE_F)*4u;
        const uint32_t vb = kb + K_F*4u;
        const int krow0 = b*SEQN + kt*KTB;
        #pragma unroll
        for (int i=0;i<4;i++){
            int j = tid + 256*i, r = j>>4, c4 = (j&15)<<2;
            cp16(kb + (uint32_t)(r*LDK + c4)*4u, &K[(size_t)(krow0+r)*DMODEL + hc + c4]);
            cp16(vb + (uint32_t)(r*LDV + c4)*4u, &V[(size_t)(krow0+r)*DMODEL + hc + c4]);
        }
        CP_COMMIT();
    };

    issue(0, 0);
    issue(1, 1);

    const int ntiles = SEQN / KTB;   // 32
    for (int t = 0; t < ntiles; ++t){
        CP_WAIT(1);
        __syncthreads();
        const float* Ks = sf + (t & 1)*STAGE_F;
        const float* Vs = Ks + K_F;

        // S = Q * K^T  (16 x 64 per warp, all keys)
        float sacc[8][4];
        #pragma unroll
        for (int i=0;i<8;i++)
            #pragma unroll
            for (int j=0;j<4;j++) sacc[i][j]=0.f;

        #pragma unroll
        for (int c = 0; c < 8; ++c){
            unsigned af[4] = { __float_as_uint(qlo[c].x), __float_as_uint(qhi[c].x),
                               __float_as_uint(qlo[c].y), __float_as_uint(qhi[c].y) };
            #pragma unroll
            for (int nf = 0; nf < 8; ++nf){
                float2 kpv = *reinterpret_cast<const float2*>(&Ks[(8*nf+group)*LDK + 8*c + 2*tig]);
                unsigned bf[2] = { __float_as_uint(kpv.x), __float_as_uint(kpv.y) };
                mma8(sacc[nf], af, bf);
            }
        }

        // online softmax (register fragments; quad shfl for row reductions)
        float mx_lo = -1e30f, mx_hi = -1e30f;
        #pragma unroll
        for (int nf=0; nf<8; nf++){
            mx_lo = fmaxf(mx_lo, fmaxf(sacc[nf][0], sacc[nf][1]));
            mx_hi = fmaxf(mx_hi, fmaxf(sacc[nf][2], sacc[nf][3]));
        }
        mx_lo = fmaxf(mx_lo, __shfl_xor_sync(0xffffffffu, mx_lo, 1));
        mx_lo = fmaxf(mx_lo, __shfl_xor_sync(0xffffffffu, mx_lo, 2));
        mx_hi = fmaxf(mx_hi, __shfl_xor_sync(0xffffffffu, mx_hi, 1));
        mx_hi = fmaxf(mx_hi, __shfl_xor_sync(0xffffffffu, mx_hi, 2));
        const float mn_lo = fmaxf(m_lo, mx_lo), mn_hi = fmaxf(m_hi, mx_hi);
        const float a_lo = ex2f(m_lo - mn_lo), a_hi = ex2f(m_hi - mn_hi);

        unsigned pa[8][4];
        float s_lo = 0.f, s_hi = 0.f;
        #pragma unroll
        for (int nf=0; nf<8; nf++){
            float p0 = ex2f(sacc[nf][0] - mn_lo);
            float p1 = ex2f(sacc[nf][1] - mn_lo);
            float p2 = ex2f(sacc[nf][2] - mn_hi);
            float p3 = ex2f(sacc[nf][3] - mn_hi);
            s_lo += p0 + p1;  s_hi += p2 + p3;
            // A-fragment order for PV: {slot tig, row+8, slot tig+4, row+8}
            pa[nf][0] = tf32r(p0); pa[nf][1] = tf32r(p2);
            pa[nf][2] = tf32r(p1); pa[nf][3] = tf32r(p3);
        }
        s_lo += __shfl_xor_sync(0xffffffffu, s_lo, 1);
        s_lo += __shfl_xor_sync(0xffffffffu, s_lo, 2);
        s_hi += __shfl_xor_sync(0xffffffffu, s_hi, 1);
        s_hi += __shfl_xor_sync(0xffffffffu, s_hi, 2);
        l_lo = l_lo*a_lo + s_lo;  m_lo = mn_lo;
        l_hi = l_hi*a_hi + s_hi;  m_hi = mn_hi;

        #pragma unroll
        for (int df=0; df<8; df++){
            oacc[df][0]*=a_lo; oacc[df][1]*=a_lo;
            oacc[df][2]*=a_hi; oacc[df][3]*=a_hi;
        }

        // O += P * V  (key relabel: slots tig,tig+4 <-> keys 8nf+2tig, 8nf+2tig+1)
        #pragma unroll
        for (int nf=0; nf<8; nf++){
            const float* v0 = &Vs[(8*nf + 2*tig  )*LDV + group];
            const float* v1 = &Vs[(8*nf + 2*tig+1)*LDV + group];
            #pragma unroll
            for (int df=0; df<8; df++){
                unsigned bf[2] = { __float_as_uint(v0[8*df]), __float_as_uint(v1[8*df]) };
                mma8(oacc[df], pa[nf], bf);
            }
        }

        __syncthreads();
        if (t + 2 < ntiles) issue(t & 1, t + 2);
        else CP_COMMIT();
    }

    // epilogue: normalize, round, interleave (A operand of the O-projection)
    const float inv_lo = 1.f / l_lo, inv_hi = 1.f / l_hi;
    const int p0 = kp8(2*tig), p1 = kp8(2*tig+1);
    const size_t r_lo = (size_t)(qrow0 + warp*16 + group);
    #pragma unroll
    for (int df=0; df<8; df++){
        const int base = hc + 8*df;
        O[r_lo*DMODEL     + base + p0] = tf32f(oacc[df][0]*inv_lo);
        O[r_lo*DMODEL     + base + p1] = tf32f(oacc[df][1]*inv_lo);
        O[(r_lo+8)*DMODEL + base + p0] = tf32f(oacc[df][2]*inv_hi);
        O[(r_lo+8)*DMODEL + base + p1] = tf32f(oacc[df][3]*inv_hi);
    }
}

// ---------------- launch ----------------
extern "C" void kernel_launch(void* const* d_in, const int* in_sizes, int n_in,
                              void* d_out, int out_size)
{
    (void)in_sizes; (void)n_in; (void)out_size;
    const float* x  = (const float*)d_in[0];
    const float* Wq = (const float*)d_in[1];
    const float* Wk = (const float*)d_in[2];
    const float* Wv = (const float*)d_in[3];
    const float* Wo = (const float*)d_in[4];
    float* out = (float*)d_out;

    float *q, *k, *v, *aout, *xr, *wqr, *wkr, *wvr, *wor;
    cudaGetSymbolAddress((void**)&q,    g_Q);
    cudaGetSymbolAddress((void**)&k,    g_K);
    cudaGetSymbolAddress((void**)&v,    g_V);
    cudaGetSymbolAddress((void**)&aout, g_Aout);
    cudaGetSymbolAddress((void**)&xr,   g_Xr);
    cudaGetSymbolAddress((void**)&wqr,  g_Wqr);
    cudaGetSymbolAddress((void**)&wkr,  g_Wkr);
    cudaGetSymbolAddress((void**)&wvr,  g_Wvr);
    cudaGetSymbolAddress((void**)&wor,  g_Wor);

    cudaFuncSetAttribute(gemm_tc2, cudaFuncAttributeMaxDynamicSharedMemorySize, GEMM_SMEM);
    cudaFuncSetAttribute(attn_flash2, cudaFuncAttributeMaxDynamicSharedMemorySize, ATTN_SMEM);

    const int NX = MTOT*DMODEL, NW = DMODEL*DMODEL;
    prep<<<NX/256, 256>>>(x,  xr,  NX);
    prep<<<NW/256, 256>>>(Wq, wqr, NW);
    prep<<<NW/256, 256>>>(Wk, wkr, NW);
    prep<<<NW/256, 256>>>(Wv, wvr, NW);
    prep<<<NW/256, 256>>>(Wo, wor, NW);

    const float qscale = 0.125f * 1.4426950408889634f;  // 1/sqrt(64) * log2(e)

    dim3 g1(DMODEL/GBN, MTOT/GBM);   // (8, 32)
    gemm_tc2<<<g1, 256, GEMM_SMEM>>>(xr, wqr, q, MTOT, DMODEL, DMODEL, 1, qscale);
    gemm_tc2<<<g1, 256, GEMM_SMEM>>>(xr, wkr, k, MTOT, DMODEL, DMODEL, 1, 1.0f);
    gemm_tc2<<<g1, 256, GEMM_SMEM>>>(xr, wvr, v, MTOT, DMODEL, DMODEL, 2, 1.0f);

    dim3 g2(SEQN/QTB, NHEAD, SEQB);  // (16, 16, 4)
    attn_flash2<<<g2, 256, ATTN_SMEM>>>(q, k, v, aout);

    gemm_tc2<<<g1, 256, GEMM_SMEM>>>(aout, wor, out, MTOT, DMODEL, DMODEL, 0, 1.0f);
}